// round 10
// baseline (speedup 1.0000x reference)
#include <cuda_runtime.h>

typedef unsigned int u32;
typedef unsigned long long u64;
typedef unsigned short u16;

#define NSEG 2621440u      // voxels per sample == template size
#define NSAMP 8
#define SEGS 9             // 8 samples + 1 template
#define TPB 256
#define IPT 16
#define TILE 4096          // TPB*IPT
#define TILES 640          // NSEG / TILE (exact)
#define BINS 2048          // 11-bit digits (pass 2 uses 10 bits -> bins 1024..2047 empty)

// Static device scratch
__device__ u64 g_bufA[(size_t)SEGS * NSEG];
__device__ u64 g_bufB[(size_t)SEGS * NSEG];
__device__ u32 g_th[3ull * SEGS * TILES * BINS];  // [plane][seg][tile][digit]  TILE-MAJOR
__device__ u32 g_ghist[3 * SEGS * BINS];          // global digit hist per (plane,seg)
__device__ u32 g_gbase[3 * SEGS * BINS];          // exclusive scan of g_ghist
__device__ float g_tval[NSEG];                    // sorted template values

__device__ __forceinline__ u32 f2k(float f) {
    u32 u = __float_as_uint(f);
    return u ^ (((u32)((int)u >> 31)) | 0x80000000u);
}
__device__ __forceinline__ float k2f(u32 u) {
    u ^= ((u & 0x80000000u) ? 0x80000000u : 0xFFFFFFFFu);
    return __uint_as_float(u);
}

// ---------------- zero global hists ----------------
__global__ void zero_k() {
    u32 i = blockIdx.x * blockDim.x + threadIdx.x;
    if (i < 3 * SEGS * BINS) g_ghist[i] = 0;
}

// ---------------- hist0: read floats; 3 global planes + pass-0 per-tile hist ----------------
__global__ void __launch_bounds__(TPB) hist0_k(const float* __restrict__ x,
                                               const float* __restrict__ t) {
    __shared__ u32 h[3 * BINS];   // 24 KB
    const int tid = threadIdx.x;
    const int l = tid & 31;
    const int seg = blockIdx.y;
    const int tile = blockIdx.x;
    for (int i = tid; i < 3 * BINS; i += TPB) h[i] = 0;
    __syncthreads();

    const float* src = (seg < NSAMP) ? (x + (size_t)seg * NSEG) : t;
    const u32 base = tile * TILE;
    #pragma unroll
    for (int k = 0; k < 4; k++) {
        u32 j = base + (u32)(k * TPB * 4) + tid * 4;
        float4 v = *reinterpret_cast<const float4*>(src + j);
        u32 kk[4] = { f2k(v.x), f2k(v.y), f2k(v.z), f2k(v.w) };
        #pragma unroll
        for (int e = 0; e < 4; e++) {
            atomicAdd(&h[kk[e] & (BINS - 1)], 1u);                 // plane 0 bits[0:11)
            atomicAdd(&h[BINS + ((kk[e] >> 11) & (BINS - 1))], 1u);// plane 1 bits[11:22)
            u32 d2 = kk[e] >> 22;                                  // plane 2 bits[22:32), skewed
            u32 m2 = __match_any_sync(0xFFFFFFFFu, d2);
            if ((int)(__ffs(m2) - 1) == l) atomicAdd(&h[2 * BINS + d2], (u32)__popc(m2));
        }
    }
    __syncthreads();
    // global hists
    for (int i = tid; i < 3 * BINS; i += TPB) {
        u32 c = h[i];
        if (c) {
            int plane = i / BINS;
            atomicAdd(&g_ghist[(plane * SEGS + seg) * BINS + (i & (BINS - 1))], c);
        }
    }
    // pass-0 per-tile hist (tile-major, coalesced)
    size_t thb = ((size_t)(0 * SEGS + seg) * TILES + tile) * BINS;
    for (int d = tid; d < BINS; d += TPB) g_th[thb + d] = h[d];
}

// ---------------- per-tile hist for passes 1/2 over u64 items (key = hi u32) ----------------
template<int PLANE, int SHIFT, bool AGG>
__global__ void __launch_bounds__(TPB) hist_k(const u64* __restrict__ srcp) {
    __shared__ u32 h[BINS];   // 8 KB
    const u32* __restrict__ in = reinterpret_cast<const u32*>(srcp);
    const int t = threadIdx.x;
    const int l = t & 31;
    const int tile = blockIdx.x, seg = blockIdx.y;
    for (int i = t; i < BINS; i += TPB) h[i] = 0;
    __syncthreads();
    const size_t base = 2 * ((size_t)seg * NSEG + (size_t)tile * TILE) + 1;
    #pragma unroll
    for (int k = 0; k < IPT; k++) {
        u32 key = __ldcs(&in[base + 2 * (size_t)(k * TPB + t)]);
        u32 d = (key >> SHIFT) & (BINS - 1);
        if (AGG) {
            u32 m = __match_any_sync(0xFFFFFFFFu, d);
            if ((int)(__ffs(m) - 1) == l) atomicAdd(&h[d], (u32)__popc(m));
        } else {
            atomicAdd(&h[d], 1u);
        }
    }
    __syncthreads();
    size_t thb = ((size_t)(PLANE * SEGS + seg) * TILES + tile) * BINS;
    for (int d = t; d < BINS; d += TPB) g_th[thb + d] = h[d];
}

// ---------------- per-(plane,seg) exclusive digit scan over 2048 bins ----------------
__global__ void __launch_bounds__(256) gscan_k() {
    __shared__ u32 wsum[8];
    const int seg = blockIdx.x, p = blockIdx.y;
    const int t = threadIdx.x, l = t & 31, w = t >> 5;
    const u32 base = (u32)(p * SEGS + seg) * BINS + t * 8;
    u32 v[8];
    #pragma unroll
    for (int i = 0; i < 8; i++) v[i] = g_ghist[base + i];
    u32 tot = 0;
    #pragma unroll
    for (int i = 0; i < 8; i++) { u32 c = v[i]; v[i] = tot; tot += c; }
    u32 sc = tot;
    #pragma unroll
    for (int off = 1; off < 32; off <<= 1) {
        u32 n = __shfl_up_sync(0xFFFFFFFFu, sc, off);
        if (l >= off) sc += n;
    }
    if (l == 31) wsum[w] = sc;
    __syncthreads();
    if (t == 0) {
        u32 run = 0;
        #pragma unroll
        for (int i = 0; i < 8; i++) { u32 c = wsum[i]; wsum[i] = run; run += c; }
    }
    __syncthreads();
    u32 ebase = wsum[w] + sc - tot;
    #pragma unroll
    for (int i = 0; i < 8; i++) g_gbase[base + i] = ebase + v[i];
}

// ---------------- tile scan: counts -> absolute offsets (in place, tile-major) ----------------
// warp handles 32 consecutive digits (lane = digit); loop over tiles; coalesced 128B per step
__global__ void __launch_bounds__(256) tscan_k(int P) {
    const int seg = blockIdx.x;
    const int t = threadIdx.x, w = t >> 5, l = t & 31;
    const u32 D = (u32)(blockIdx.y * 8 + w) * 32 + l;
    u32 run = g_gbase[(u32)(P * SEGS + seg) * BINS + D];
    size_t base = ((size_t)(P * SEGS + seg) * TILES) * BINS + D;
    #pragma unroll 4
    for (int tile = 0; tile < TILES; tile++) {
        size_t a = base + (size_t)tile * BINS;
        u32 v = g_th[a];
        g_th[a] = run;
        run += v;
    }
}

// ---------------- scatter: match+atomic warp-pair ranking, direct store ----------------
// SRC 0: floats (key=f2k, payload=index)   SRC 1: u64 items
// MODE 0: u64 -> outp    MODE 1: out[idx] = g_tval[pos]    MODE 2: g_tval[pos] = key
template<int SRC, int PLANE, int SHIFT, int MODE>
__global__ void __launch_bounds__(TPB) scat_k(const float* __restrict__ xf,
                                              const float* __restrict__ bvf,
                                              const u64* __restrict__ in,
                                              u64* __restrict__ outp,
                                              float* __restrict__ outf,
                                              int segOff) {
    __shared__ u32 pc[BINS * 4];     // 32 KB: packed u16 halves, word = [digit][warp-pair]
    __shared__ u32 delta[BINS];      // 8 KB: absolute base per digit for this tile

    const int t = threadIdx.x;
    const int w = t >> 5;            // 0..7
    const int l = t & 31;
    const u32 lmlt = (1u << l) - 1u;
    const u32 tile = blockIdx.x;
    const int seg = blockIdx.y + segOff;
    const u32 sh16 = (u32)(w & 1) * 16;
    const int pairo = w >> 1;
    const size_t sbase = (size_t)seg * NSEG;

    // zero counters + load delta (coalesced)
    #pragma unroll
    for (int i = 0; i < (BINS * 4) / TPB; i++) pc[i * TPB + t] = 0;
    const size_t thb = ((size_t)(PLANE * SEGS + seg) * TILES + tile) * BINS;
    #pragma unroll
    for (int i = 0; i < BINS / TPB; i++) delta[i * TPB + t] = g_th[thb + (u32)i * TPB + t];
    __syncthreads();

    // load items warp-major: j = w*512 + k*32 + l (stable order == index order)
    u32 key[IPT];
    u32 pay[IPT];
    const u32 jb = tile * TILE + (u32)w * (IPT * 32);
    if (SRC == 0) {
        const float* s = (seg < NSAMP) ? (xf + sbase) : bvf;
        #pragma unroll
        for (int k = 0; k < IPT; k++) {
            key[k] = f2k(__ldcs(&s[jb + (u32)k * 32 + l]));
            pay[k] = jb + (u32)k * 32 + l;
        }
    } else {
        #pragma unroll
        for (int k = 0; k < IPT; k++) {
            u64 it = __ldcs(&in[sbase + jb + (u32)k * 32 + l]);
            key[k] = (u32)(it >> 32);
            pay[k] = (u32)it;
        }
    }

    // rank: per round, leader atomically bumps its warp's packed half; old = warp prefix
    u16 pp[IPT];
    #pragma unroll
    for (int k = 0; k < IPT; k++) {
        u32 d = (key[k] >> SHIFT) & (BINS - 1);
        u32 m = __match_any_sync(0xFFFFFFFFu, d);
        int leader = (int)(__ffs(m) - 1);
        u32 r = __popc(m & lmlt);
        u32 old = 0;
        if (l == leader)
            old = (atomicAdd(&pc[d * 4 + pairo], (u32)__popc(m) << sh16) >> sh16) & 0xFFFFu;
        old = __shfl_sync(0xFFFFFFFFu, old, leader);
        pp[k] = (u16)(old + r);
    }
    __syncthreads();

    // cross-warp exclusive scan per digit: 4 packed words -> warp-prefix (in place)
    #pragma unroll
    for (int i = 0; i < BINS / TPB; i++) {
        u32 d = (u32)i * TPB + t;
        u32 run = 0;
        #pragma unroll
        for (int p = 0; p < 4; p++) {
            u32 wd = pc[d * 4 + p];
            u32 c0 = wd & 0xFFFFu, c1 = wd >> 16;
            pc[d * 4 + p] = run | ((run + c0) << 16);
            run += c0 + c1;
        }
    }
    __syncthreads();

    // final positions, direct write
    #pragma unroll
    for (int k = 0; k < IPT; k++) {
        u32 d = (key[k] >> SHIFT) & (BINS - 1);
        u32 wb = (pc[d * 4 + pairo] >> sh16) & 0xFFFFu;
        u32 pos = delta[d] + wb + (u32)pp[k];
        if (MODE == 0) {
            outp[sbase + pos] = ((u64)key[k] << 32) | pay[k];
        } else if (MODE == 2) {
            g_tval[pos] = k2f(key[k]);
        } else {
            outf[sbase + pay[k]] = __ldg(&g_tval[pos]);
        }
    }
}

extern "C" void kernel_launch(void* const* d_in, const int* in_sizes, int n_in,
                              void* d_out, int out_size) {
    const float* x  = (const float*)d_in[0];
    const float* bv = (const float*)d_in[1];
    float* out = (float*)d_out;

    zero_k<<<(3 * SEGS * BINS + 255) / 256, 256>>>();
    hist0_k<<<dim3(TILES, SEGS), TPB>>>(x, bv);
    gscan_k<<<dim3(SEGS, 3), 256>>>();

    // pass 0: bits[0:11)  floats -> A
    tscan_k<<<dim3(SEGS, 8), 256>>>(0);
    scat_k<0, 0, 0, 0><<<dim3(TILES, SEGS), TPB>>>(x, bv, nullptr, g_bufA, nullptr, 0);

    // pass 1: bits[11:22)  A -> B
    hist_k<1, 11, false><<<dim3(TILES, SEGS), TPB>>>(g_bufA);
    tscan_k<<<dim3(SEGS, 8), 256>>>(1);
    scat_k<1, 1, 11, 0><<<dim3(TILES, SEGS), TPB>>>(nullptr, nullptr, g_bufA, g_bufB, nullptr, 0);

    // pass 2: bits[22:32)  B -> final
    hist_k<2, 22, true><<<dim3(TILES, SEGS), TPB>>>(g_bufB);
    tscan_k<<<dim3(SEGS, 8), 256>>>(2);
    scat_k<1, 2, 22, 2><<<dim3(TILES, 1), TPB>>>(nullptr, nullptr, g_bufB, nullptr, nullptr, NSAMP); // template -> g_tval
    scat_k<1, 2, 22, 1><<<dim3(TILES, NSAMP), TPB>>>(nullptr, nullptr, g_bufB, nullptr, out, 0);     // fused epilogue
}

// round 11
// speedup vs baseline: 20.3674x; 20.3674x over previous
#include <cuda_runtime.h>

typedef unsigned int u32;
typedef unsigned long long u64;
typedef unsigned char u8;

#define NSEG 2621440u      // voxels per sample == template size
#define NSAMP 8
#define SEGS 9             // 8 samples + 1 template
#define TPB 256
#define IPT 8
#define TILE 2048          // TPB*IPT
#define TILES 1280         // NSEG / TILE (exact)

// Static device scratch
__device__ u64 g_bufA[(size_t)SEGS * NSEG];
__device__ u64 g_bufB[(size_t)SEGS * NSEG];
__device__ u32 g_th[4ull * SEGS * 256 * TILES];  // [pass][seg][digit][tile] counts -> abs offsets
__device__ u32 g_ghist[4 * SEGS * 256];          // global digit hist per (pass,seg)
__device__ u32 g_gbase[4 * SEGS * 256];          // exclusive scan of g_ghist
__device__ float g_tval[NSEG];                   // sorted template values

__device__ __forceinline__ u32 f2k(float f) {
    u32 u = __float_as_uint(f);
    return u ^ ((u & 0x80000000u) ? 0xFFFFFFFFu : 0x80000000u);
}
__device__ __forceinline__ float k2f(u32 u) {
    u ^= ((u & 0x80000000u) ? 0x80000000u : 0xFFFFFFFFu);
    return __uint_as_float(u);
}

// ---------------- zero global hists ----------------
__global__ void zero_k() {
    u32 i = blockIdx.x * blockDim.x + threadIdx.x;
    if (i < 4 * SEGS * 256) g_ghist[i] = 0;
}

// ---------------- fused pack + global 4-plane hist + pass-0 per-tile hist ----------------
__global__ void __launch_bounds__(TPB) pack_hist_k(const float* __restrict__ x,
                                                   const float* __restrict__ t) {
    __shared__ u32 h[4][256];
    const int tid = threadIdx.x;
    const int l = tid & 31;
    const int seg = blockIdx.y;
    const int tile = blockIdx.x;
    for (int i = tid; i < 4 * 256; i += TPB) (&h[0][0])[i] = 0;
    __syncthreads();

    const float* src = (seg < NSAMP) ? (x + (size_t)seg * NSEG) : t;
    u64* dst = g_bufA + (size_t)seg * NSEG;
    const u32 base = tile * TILE;
    #pragma unroll
    for (int k = 0; k < 2; k++) {       // 2 * 256 threads * 4 = 2048 = TILE
        u32 j = base + (u32)(k * TPB * 4) + tid * 4;
        float4 v = *reinterpret_cast<const float4*>(src + j);
        u32 kk[4] = { f2k(v.x), f2k(v.y), f2k(v.z), f2k(v.w) };
        #pragma unroll
        for (int e = 0; e < 4; e++) {
            dst[j + e] = ((u64)kk[e] << 32) | (j + e);
            atomicAdd(&h[0][kk[e] & 255u], 1u);
            atomicAdd(&h[1][(kk[e] >> 8) & 255u], 1u);
            u32 d2 = (kk[e] >> 16) & 255u;
            u32 m2 = __match_any_sync(0xFFFFFFFFu, d2);
            if ((int)(__ffs(m2) - 1) == l) atomicAdd(&h[2][d2], (u32)__popc(m2));
            u32 d3 = kk[e] >> 24;
            u32 m3 = __match_any_sync(0xFFFFFFFFu, d3);
            if ((int)(__ffs(m3) - 1) == l) atomicAdd(&h[3][d3], (u32)__popc(m3));
        }
    }
    __syncthreads();
    #pragma unroll
    for (int p = 0; p < 4; p++) {
        u32 c = h[p][tid];
        if (c) atomicAdd(&g_ghist[(p * SEGS + seg) * 256 + tid], c);
    }
    g_th[((size_t)(0 * SEGS + seg) * 256 + tid) * TILES + tile] = h[0][tid];
}

// ---------------- per-tile hist for passes 1..3 (reads key u32 only) ----------------
template<int PASS>
__global__ void __launch_bounds__(TPB) hist_k() {
    __shared__ u32 h[8][256];
    const u32* __restrict__ in = reinterpret_cast<const u32*>((PASS & 1) ? g_bufB : g_bufA);
    const int t = threadIdx.x;
    const int w = t >> 5;
    const int tile = blockIdx.x, seg = blockIdx.y;
    #pragma unroll
    for (int i = t; i < 8 * 256; i += TPB) (&h[0][0])[i] = 0;
    __syncthreads();
    const size_t base = 2 * ((size_t)seg * NSEG + (size_t)tile * TILE) + 1;
    #pragma unroll
    for (int k = 0; k < IPT; k++) {
        u32 key = __ldcs(&in[base + 2 * (size_t)(k * TPB + t)]);
        atomicAdd(&h[w][(key >> (8 * PASS)) & 255u], 1u);
    }
    __syncthreads();
    u32 s = 0;
    #pragma unroll
    for (int w2 = 0; w2 < 8; w2++) s += h[w2][t];
    g_th[((size_t)(PASS * SEGS + seg) * 256 + t) * TILES + tile] = s;
}

// ---------------- per-(pass,seg) exclusive digit scan ----------------
__global__ void gscan_k() {
    __shared__ u32 wsum[8];
    const int seg = blockIdx.x, p = blockIdx.y;
    const int t = threadIdx.x, l = t & 31, w = t >> 5;
    u32 tot = g_ghist[(p * SEGS + seg) * 256 + t];
    u32 v = tot;
    #pragma unroll
    for (int off = 1; off < 32; off <<= 1) {
        u32 n = __shfl_up_sync(0xFFFFFFFFu, v, off);
        if (l >= off) v += n;
    }
    if (l == 31) wsum[w] = v;
    __syncthreads();
    if (t == 0) {
        u32 run = 0;
        #pragma unroll
        for (int i = 0; i < 8; i++) { u32 c = wsum[i]; wsum[i] = run; run += c; }
    }
    __syncthreads();
    g_gbase[(p * SEGS + seg) * 256 + t] = wsum[w] + v - tot;
}

// ---------------- per-(seg,digit) scan over tiles (digit-major rows, coalesced) ----------------
__global__ void __launch_bounds__(256) tscan_k(int P) {
    const int seg = blockIdx.x;
    const int t = threadIdx.x, w = t >> 5, l = t & 31;
    const int d = blockIdx.y * 8 + w;
    u32* row = g_th + ((size_t)(P * SEGS + seg) * 256 + d) * TILES;
    u32 run = g_gbase[(P * SEGS + seg) * 256 + d];
    for (int c = 0; c < TILES; c += 32) {
        u32 v = row[c + l];
        u32 s = v;
        #pragma unroll
        for (int off = 1; off < 32; off <<= 1) {
            u32 n = __shfl_up_sync(0xFFFFFFFFu, s, off);
            if (l >= off) s += n;
        }
        row[c + l] = run + s - v;          // exclusive absolute offset
        run += __shfl_sync(0xFFFFFFFFu, s, 31);
    }
}

// ---------------- stable rank + direct scatter (R5 engine, IPT=8, 4 CTAs/SM) ----------------
// MODE 0: sorted u64 items -> other buffer
// MODE 1: fused epilogue  out[idx] = t_sorted[pos]   (samples, pass 3)
// MODE 2: g_tval[pos] = key-as-float                 (template, pass 3)
template<int PASS, int MODE>
__global__ void __launch_bounds__(TPB, 4) scatter_k(float* __restrict__ outf, int segOff) {
    __shared__ u8 cnt8[IPT * 8 * 256];   // 16 KB: per (round,warp,digit) counts -> warp prefixes
    __shared__ u32 rb[IPT * 256];        // 8 KB: absolute base per (round, digit)

    const int t = threadIdx.x;
    const int w = t >> 5;
    const int l = t & 31;
    const u32 lmlt = (1u << l) - 1u;
    const u32 tile = blockIdx.x;
    const int seg = blockIdx.y + segOff;
    constexpr int SHIFT = 32 + 8 * PASS;

    const u64* __restrict__ in = (PASS & 1) ? g_bufB : g_bufA;
    u64* __restrict__ outp     = (PASS & 1) ? g_bufA : g_bufB;
    const size_t sbase = (size_t)seg * NSEG;
    const size_t base = sbase + (size_t)tile * TILE;

    // issue global loads early (striped; streaming hint)
    u64 item[IPT];
    #pragma unroll
    for (int k = 0; k < IPT; k++) item[k] = __ldcs(&in[base + (size_t)k * TPB + t]);

    // absolute digit base for this (seg, digit t, tile) — precomputed, no lookback
    u32 run = g_th[((size_t)(PASS * SEGS + seg) * 256 + t) * TILES + tile];

    // zero counters
    u32* c32 = reinterpret_cast<u32*>(cnt8);
    #pragma unroll
    for (int i = 0; i < (IPT * 8 * 256 / 4) / TPB; i++) c32[i * TPB + t] = 0;
    __syncthreads();

    // warp match ranking; leaders record per-(round,warp,digit) counts
    u32 lr0 = 0, lr1 = 0;
    #pragma unroll
    for (int k = 0; k < IPT; k++) {
        u32 d = (u32)(item[k] >> SHIFT) & 255u;
        u32 m = __match_any_sync(0xFFFFFFFFu, d);
        u32 r = __popc(m & lmlt);
        if (r == 0) cnt8[(k * 8 + w) * 256 + d] = (u8)__popc(m);
        if (k < 4) lr0 |= r << (8 * k);
        else       lr1 |= r << (8 * (k - 4));
    }
    __syncthreads();

    // thread t owns digit t; serial prefix over 64 (round, warp) cells
    #pragma unroll
    for (int k = 0; k < IPT; k++) {
        rb[k * 256 + t] = run;
        u32 rs = run;
        #pragma unroll
        for (int w2 = 0; w2 < 8; w2++) {
            u32 i = (u32)(k * 8 + w2) * 256 + t;
            u32 c = cnt8[i];
            cnt8[i] = (u8)(run - rs);   // warp prefix relative to round start (<= 224)
            run += c;
        }
    }
    __syncthreads();

    // final positions, direct global write
    #pragma unroll
    for (int k = 0; k < IPT; k++) {
        u32 d = (u32)(item[k] >> SHIFT) & 255u;
        u32 r = (k < 4) ? ((lr0 >> (8 * k)) & 255u) : ((lr1 >> (8 * (k - 4))) & 255u);
        u32 pos = rb[k * 256 + d] + (u32)cnt8[(k * 8 + w) * 256 + d] + r;
        if (MODE == 0) {
            outp[sbase + pos] = item[k];
        } else if (MODE == 2) {
            g_tval[pos] = k2f((u32)(item[k] >> 32));
        } else {
            outf[sbase + (u32)item[k]] = __ldg(&g_tval[pos]);
        }
    }
}

extern "C" void kernel_launch(void* const* d_in, const int* in_sizes, int n_in,
                              void* d_out, int out_size) {
    const float* x  = (const float*)d_in[0];
    const float* bv = (const float*)d_in[1];
    float* out = (float*)d_out;

    zero_k<<<36, 256>>>();
    pack_hist_k<<<dim3(TILES, SEGS), TPB>>>(x, bv);
    gscan_k<<<dim3(SEGS, 4), 256>>>();

    tscan_k<<<dim3(SEGS, 32), 256>>>(0);
    scatter_k<0, 0><<<dim3(TILES, SEGS), TPB>>>(nullptr, 0);   // A -> B

    hist_k<1><<<dim3(TILES, SEGS), TPB>>>();
    tscan_k<<<dim3(SEGS, 32), 256>>>(1);
    scatter_k<1, 0><<<dim3(TILES, SEGS), TPB>>>(nullptr, 0);   // B -> A

    hist_k<2><<<dim3(TILES, SEGS), TPB>>>();
    tscan_k<<<dim3(SEGS, 32), 256>>>(2);
    scatter_k<2, 0><<<dim3(TILES, SEGS), TPB>>>(nullptr, 0);   // A -> B

    hist_k<3><<<dim3(TILES, SEGS), TPB>>>();
    tscan_k<<<dim3(SEGS, 32), 256>>>(3);
    scatter_k<3, 2><<<dim3(TILES, 1), TPB>>>(nullptr, NSAMP);  // template -> g_tval
    scatter_k<3, 1><<<dim3(TILES, NSAMP), TPB>>>(out, 0);      // fused epilogue
}

// round 12
// speedup vs baseline: 21.8048x; 1.0706x over previous
#include <cuda_runtime.h>

typedef unsigned int u32;
typedef unsigned long long u64;
typedef unsigned char u8;

#define NSEG 2621440u      // voxels per sample == template size
#define NSAMP 8
#define SEGS 9             // 8 samples + 1 template
#define TPB 256
#define IPT 16
#define TILE 4096          // TPB*IPT
#define TILES 640          // NSEG / TILE (exact)
#define ROWB 132           // padded bytes per digit row (33 words -> conflict-free)

// Static device scratch
__device__ u64 g_bufA[(size_t)SEGS * NSEG];
__device__ u64 g_bufB[(size_t)SEGS * NSEG];
__device__ u32 g_th[4ull * SEGS * 256 * TILES];  // [pass][seg][digit][tile] counts -> abs offsets
__device__ u32 g_ghist[4 * SEGS * 256];          // global digit hist per (pass,seg)
__device__ u32 g_gbase[4 * SEGS * 256];          // exclusive scan of g_ghist
__device__ float g_tval[NSEG];                   // sorted template values

__device__ __forceinline__ u32 f2k(float f) {
    u32 u = __float_as_uint(f);
    return u ^ ((u & 0x80000000u) ? 0xFFFFFFFFu : 0x80000000u);
}
__device__ __forceinline__ float k2f(u32 u) {
    u ^= ((u & 0x80000000u) ? 0x80000000u : 0xFFFFFFFFu);
    return __uint_as_float(u);
}

// ---------------- zero global hists ----------------
__global__ void zero_k() {
    u32 i = blockIdx.x * blockDim.x + threadIdx.x;
    if (i < 4 * SEGS * 256) g_ghist[i] = 0;
}

// ---------------- fused pack + global 4-plane hist + pass-0 per-tile hist ----------------
__global__ void __launch_bounds__(TPB) pack_hist_k(const float* __restrict__ x,
                                                   const float* __restrict__ t) {
    __shared__ u32 h[4][256];
    const int tid = threadIdx.x;
    const int l = tid & 31;
    const int seg = blockIdx.y;
    const int tile = blockIdx.x;
    for (int i = tid; i < 4 * 256; i += TPB) (&h[0][0])[i] = 0;
    __syncthreads();

    const float* src = (seg < NSAMP) ? (x + (size_t)seg * NSEG) : t;
    u64* dst = g_bufA + (size_t)seg * NSEG;
    const u32 base = tile * TILE;
    #pragma unroll
    for (int k = 0; k < 4; k++) {
        u32 j = base + (u32)(k * TPB * 4) + tid * 4;
        float4 v = *reinterpret_cast<const float4*>(src + j);
        u32 kk[4] = { f2k(v.x), f2k(v.y), f2k(v.z), f2k(v.w) };
        #pragma unroll
        for (int e = 0; e < 4; e++) {
            dst[j + e] = ((u64)kk[e] << 32) | (j + e);
            atomicAdd(&h[0][kk[e] & 255u], 1u);
            atomicAdd(&h[1][(kk[e] >> 8) & 255u], 1u);
            u32 d2 = (kk[e] >> 16) & 255u;
            u32 m2 = __match_any_sync(0xFFFFFFFFu, d2);
            if ((int)(__ffs(m2) - 1) == l) atomicAdd(&h[2][d2], (u32)__popc(m2));
            u32 d3 = kk[e] >> 24;
            u32 m3 = __match_any_sync(0xFFFFFFFFu, d3);
            if ((int)(__ffs(m3) - 1) == l) atomicAdd(&h[3][d3], (u32)__popc(m3));
        }
    }
    __syncthreads();
    #pragma unroll
    for (int p = 0; p < 4; p++) {
        u32 c = h[p][tid];
        if (c) atomicAdd(&g_ghist[(p * SEGS + seg) * 256 + tid], c);
    }
    g_th[((size_t)(0 * SEGS + seg) * 256 + tid) * TILES + tile] = h[0][tid];
}

// ---------------- per-tile hist for passes 1..3 (reads key u32 only) ----------------
template<int PASS>
__global__ void __launch_bounds__(TPB) hist_k() {
    __shared__ u32 h[8][256];
    const u32* __restrict__ in = reinterpret_cast<const u32*>((PASS & 1) ? g_bufB : g_bufA);
    const int t = threadIdx.x;
    const int w = t >> 5;
    const int tile = blockIdx.x, seg = blockIdx.y;
    #pragma unroll
    for (int i = t; i < 8 * 256; i += TPB) (&h[0][0])[i] = 0;
    __syncthreads();
    const size_t base = 2 * ((size_t)seg * NSEG + (size_t)tile * TILE) + 1;
    #pragma unroll
    for (int k = 0; k < IPT; k++) {
        u32 key = __ldcs(&in[base + 2 * (size_t)(k * TPB + t)]);
        atomicAdd(&h[w][(key >> (8 * PASS)) & 255u], 1u);
    }
    __syncthreads();
    u32 s = 0;
    #pragma unroll
    for (int w2 = 0; w2 < 8; w2++) s += h[w2][t];
    g_th[((size_t)(PASS * SEGS + seg) * 256 + t) * TILES + tile] = s;
}

// ---------------- per-(pass,seg) exclusive digit scan ----------------
__global__ void gscan_k() {
    __shared__ u32 wsum[8];
    const int seg = blockIdx.x, p = blockIdx.y;
    const int t = threadIdx.x, l = t & 31, w = t >> 5;
    u32 tot = g_ghist[(p * SEGS + seg) * 256 + t];
    u32 v = tot;
    #pragma unroll
    for (int off = 1; off < 32; off <<= 1) {
        u32 n = __shfl_up_sync(0xFFFFFFFFu, v, off);
        if (l >= off) v += n;
    }
    if (l == 31) wsum[w] = v;
    __syncthreads();
    if (t == 0) {
        u32 run = 0;
        #pragma unroll
        for (int i = 0; i < 8; i++) { u32 c = wsum[i]; wsum[i] = run; run += c; }
    }
    __syncthreads();
    g_gbase[(p * SEGS + seg) * 256 + t] = wsum[w] + v - tot;
}

// ---------------- per-(seg,digit) scan over tiles (digit-major rows, coalesced) ----------------
__global__ void __launch_bounds__(256) tscan_k(int P) {
    const int seg = blockIdx.x;
    const int t = threadIdx.x, w = t >> 5, l = t & 31;
    const int d = blockIdx.y * 8 + w;
    u32* row = g_th + ((size_t)(P * SEGS + seg) * 256 + d) * TILES;
    u32 run = g_gbase[(P * SEGS + seg) * 256 + d];
    for (int c = 0; c < TILES; c += 32) {
        u32 v = row[c + l];
        u32 s = v;
        #pragma unroll
        for (int off = 1; off < 32; off <<= 1) {
            u32 n = __shfl_up_sync(0xFFFFFFFFu, s, off);
            if (l >= off) s += n;
        }
        row[c + l] = run + s - v;          // exclusive absolute offset
        run += __shfl_sync(0xFFFFFFFFu, s, 31);
    }
}

// ---------------- stable rank + direct scatter (R5 engine + SIMD byte-prefix) ----------------
// counters: digit-major rows, ROWB bytes/row; cell index within row = k*8 + w
// MODE 0: sorted u64 items -> other buffer
// MODE 1: fused epilogue  out[idx] = t_sorted[pos]   (samples, pass 3)
// MODE 2: g_tval[pos] = key-as-float                 (template, pass 3)
template<int PASS, int MODE>
__global__ void __launch_bounds__(TPB, 3) scatter_k(float* __restrict__ outf, int segOff) {
    __shared__ __align__(16) u32 cnt32[256 * ROWB / 4];   // 33 KB, digit-major, padded rows
    __shared__ u32 rb[IPT * 256];                         // 16 KB: abs base per (round, digit)
    u8* cnt8 = reinterpret_cast<u8*>(cnt32);

    const int t = threadIdx.x;
    const int w = t >> 5;
    const int l = t & 31;
    const u32 lmlt = (1u << l) - 1u;
    const u32 tile = blockIdx.x;
    const int seg = blockIdx.y + segOff;
    constexpr int SHIFT = 32 + 8 * PASS;

    const u64* __restrict__ in = (PASS & 1) ? g_bufB : g_bufA;
    u64* __restrict__ outp     = (PASS & 1) ? g_bufA : g_bufB;
    const size_t sbase = (size_t)seg * NSEG;
    const size_t base = sbase + (size_t)tile * TILE;

    // issue global loads early (striped; streaming hint)
    u64 item[IPT];
    #pragma unroll
    for (int k = 0; k < IPT; k++) item[k] = __ldcs(&in[base + (size_t)k * TPB + t]);

    // absolute digit base for this (seg, digit t, tile) — precomputed, no lookback
    u32 run = g_th[((size_t)(PASS * SEGS + seg) * 256 + t) * TILES + tile];

    // zero counters (256*33 = 8448 words = 33 per thread)
    #pragma unroll
    for (int i = 0; i < (256 * ROWB / 4) / TPB; i++) cnt32[i * TPB + t] = 0;
    __syncthreads();

    // warp match ranking; leaders record per-(round,warp,digit) counts
    u32 lr0 = 0, lr1 = 0, lr2 = 0, lr3 = 0;
    #pragma unroll
    for (int k = 0; k < IPT; k++) {
        u32 d = (u32)(item[k] >> SHIFT) & 255u;
        u32 m = __match_any_sync(0xFFFFFFFFu, d);
        u32 r = __popc(m & lmlt);
        if (r == 0) cnt8[d * ROWB + k * 8 + w] = (u8)__popc(m);
        if (k < 4)       lr0 |= r << (8 * k);
        else if (k < 8)  lr1 |= r << (8 * (k - 4));
        else if (k < 12) lr2 |= r << (8 * (k - 8));
        else             lr3 |= r << (8 * (k - 12));
    }
    __syncthreads();

    // thread t owns digit t: SIMD byte-prefix over 16 rounds x 2 words
    {
        const u32 rowW = (u32)t * (ROWB / 4);
        #pragma unroll
        for (int k = 0; k < IPT; k++) {
            rb[k * 256 + t] = run;
            u32 w0 = cnt32[rowW + k * 2];
            u32 w1 = cnt32[rowW + k * 2 + 1];
            u32 s0 = w0 * 0x01010101u;           // inclusive byte prefix of cells 0..3
            u32 s1 = w1 * 0x01010101u;           // inclusive byte prefix of cells 4..7
            u32 sum0 = s0 >> 24;
            cnt32[rowW + k * 2]     = s0 << 8;                       // exclusive prefixes
            cnt32[rowW + k * 2 + 1] = (s1 << 8) + sum0 * 0x01010101u;
            run += sum0 + (s1 >> 24);
        }
    }
    __syncthreads();

    // final positions, direct global write
    #pragma unroll
    for (int k = 0; k < IPT; k++) {
        u32 d = (u32)(item[k] >> SHIFT) & 255u;
        u32 r;
        if (k < 4)       r = (lr0 >> (8 * k)) & 255u;
        else if (k < 8)  r = (lr1 >> (8 * (k - 4))) & 255u;
        else if (k < 12) r = (lr2 >> (8 * (k - 8))) & 255u;
        else             r = (lr3 >> (8 * (k - 12))) & 255u;
        u32 pos = rb[k * 256 + d] + (u32)cnt8[d * ROWB + k * 8 + w] + r;
        if (MODE == 0) {
            outp[sbase + pos] = item[k];
        } else if (MODE == 2) {
            g_tval[pos] = k2f((u32)(item[k] >> 32));
        } else {
            outf[sbase + (u32)item[k]] = __ldg(&g_tval[pos]);
        }
    }
}

extern "C" void kernel_launch(void* const* d_in, const int* in_sizes, int n_in,
                              void* d_out, int out_size) {
    const float* x  = (const float*)d_in[0];
    const float* bv = (const float*)d_in[1];
    float* out = (float*)d_out;

    zero_k<<<36, 256>>>();
    pack_hist_k<<<dim3(TILES, SEGS), TPB>>>(x, bv);
    gscan_k<<<dim3(SEGS, 4), 256>>>();

    tscan_k<<<dim3(SEGS, 32), 256>>>(0);
    scatter_k<0, 0><<<dim3(TILES, SEGS), TPB>>>(nullptr, 0);   // A -> B

    hist_k<1><<<dim3(TILES, SEGS), TPB>>>();
    tscan_k<<<dim3(SEGS, 32), 256>>>(1);
    scatter_k<1, 0><<<dim3(TILES, SEGS), TPB>>>(nullptr, 0);   // B -> A

    hist_k<2><<<dim3(TILES, SEGS), TPB>>>();
    tscan_k<<<dim3(SEGS, 32), 256>>>(2);
    scatter_k<2, 0><<<dim3(TILES, SEGS), TPB>>>(nullptr, 0);   // A -> B

    hist_k<3><<<dim3(TILES, SEGS), TPB>>>();
    tscan_k<<<dim3(SEGS, 32), 256>>>(3);
    scatter_k<3, 2><<<dim3(TILES, 1), TPB>>>(nullptr, NSAMP);  // template -> g_tval
    scatter_k<3, 1><<<dim3(TILES, NSAMP), TPB>>>(out, 0);      // fused epilogue
}

// round 13
// speedup vs baseline: 27.5782x; 1.2648x over previous
#include <cuda_runtime.h>

typedef unsigned int u32;
typedef unsigned long long u64;
typedef unsigned char u8;

#define NSEG 2621440u      // voxels per sample == template size
#define NSAMP 8
#define SEGS 9             // 8 samples + 1 template
#define TPB 256
#define IPT 16
#define TILE 4096          // TPB*IPT
#define TILES 640          // NSEG / TILE (exact)
#define ROWB 132           // padded bytes per digit row (33 words -> conflict-free)

// Static device scratch
__device__ u64 g_bufA[(size_t)SEGS * NSEG];
__device__ u64 g_bufB[(size_t)SEGS * NSEG];
__device__ u32 g_th[4ull * SEGS * 256 * TILES];  // [pass][seg][digit][tile] counts -> abs offsets
__device__ u32 g_ghist[4 * SEGS * 256];          // global digit hist per (pass,seg)
__device__ u32 g_gbase[4 * SEGS * 256];          // exclusive scan of g_ghist
__device__ float g_tval[NSEG];                   // sorted template values

__device__ __forceinline__ u32 f2k(float f) {
    u32 u = __float_as_uint(f);
    return u ^ ((u & 0x80000000u) ? 0xFFFFFFFFu : 0x80000000u);
}
__device__ __forceinline__ float k2f(u32 u) {
    u ^= ((u & 0x80000000u) ? 0x80000000u : 0xFFFFFFFFu);
    return __uint_as_float(u);
}

// ---------------- zero global hists ----------------
__global__ void zero_k() {
    u32 i = blockIdx.x * blockDim.x + threadIdx.x;
    if (i < 4 * SEGS * 256) g_ghist[i] = 0;
}

// ---------------- fused pack + global hists (planes 1..3) + plane-1 per-tile hist ----------------
__global__ void __launch_bounds__(TPB) pack_hist_k(const float* __restrict__ x,
                                                   const float* __restrict__ t) {
    __shared__ u32 h[3][256];   // planes 1,2,3
    const int tid = threadIdx.x;
    const int l = tid & 31;
    const int seg = blockIdx.y;
    const int tile = blockIdx.x;
    for (int i = tid; i < 3 * 256; i += TPB) (&h[0][0])[i] = 0;
    __syncthreads();

    const float* src = (seg < NSAMP) ? (x + (size_t)seg * NSEG) : t;
    u64* dst = g_bufA + (size_t)seg * NSEG;
    const u32 base = tile * TILE;
    #pragma unroll
    for (int k = 0; k < 4; k++) {
        u32 j = base + (u32)(k * TPB * 4) + tid * 4;
        float4 v = *reinterpret_cast<const float4*>(src + j);
        u32 kk[4] = { f2k(v.x), f2k(v.y), f2k(v.z), f2k(v.w) };
        #pragma unroll
        for (int e = 0; e < 4; e++) {
            dst[j + e] = ((u64)kk[e] << 32) | (j + e);
            atomicAdd(&h[0][(kk[e] >> 8) & 255u], 1u);   // plane 1 (byte 1)
            u32 d2 = (kk[e] >> 16) & 255u;               // plane 2 (skewed): aggregate
            u32 m2 = __match_any_sync(0xFFFFFFFFu, d2);
            if ((int)(__ffs(m2) - 1) == l) atomicAdd(&h[1][d2], (u32)__popc(m2));
            u32 d3 = kk[e] >> 24;                        // plane 3 (skewed): aggregate
            u32 m3 = __match_any_sync(0xFFFFFFFFu, d3);
            if ((int)(__ffs(m3) - 1) == l) atomicAdd(&h[2][d3], (u32)__popc(m3));
        }
    }
    __syncthreads();
    #pragma unroll
    for (int p = 0; p < 3; p++) {
        u32 c = h[p][tid];
        if (c) atomicAdd(&g_ghist[((p + 1) * SEGS + seg) * 256 + tid], c);
    }
    // plane-1 per-tile hist (first sort pass)
    g_th[((size_t)(1 * SEGS + seg) * 256 + tid) * TILES + tile] = h[0][tid];
}

// ---------------- per-tile hist for passes 2..3 (reads key u32 only) ----------------
// parity: pass1 A->B, pass2 B->A, pass3 A->out  =>  input = (PASS&1) ? A : B
template<int PASS>
__global__ void __launch_bounds__(TPB) hist_k() {
    __shared__ u32 h[8][256];
    const u32* __restrict__ in = reinterpret_cast<const u32*>((PASS & 1) ? g_bufA : g_bufB);
    const int t = threadIdx.x;
    const int w = t >> 5;
    const int tile = blockIdx.x, seg = blockIdx.y;
    #pragma unroll
    for (int i = t; i < 8 * 256; i += TPB) (&h[0][0])[i] = 0;
    __syncthreads();
    const size_t base = 2 * ((size_t)seg * NSEG + (size_t)tile * TILE) + 1;
    #pragma unroll
    for (int k = 0; k < IPT; k++) {
        u32 key = __ldcs(&in[base + 2 * (size_t)(k * TPB + t)]);
        atomicAdd(&h[w][(key >> (8 * PASS)) & 255u], 1u);
    }
    __syncthreads();
    u32 s = 0;
    #pragma unroll
    for (int w2 = 0; w2 < 8; w2++) s += h[w2][t];
    g_th[((size_t)(PASS * SEGS + seg) * 256 + t) * TILES + tile] = s;
}

// ---------------- per-(pass,seg) exclusive digit scan (planes 1..3) ----------------
__global__ void gscan_k() {
    __shared__ u32 wsum[8];
    const int seg = blockIdx.x, p = blockIdx.y + 1;
    const int t = threadIdx.x, l = t & 31, w = t >> 5;
    u32 tot = g_ghist[(p * SEGS + seg) * 256 + t];
    u32 v = tot;
    #pragma unroll
    for (int off = 1; off < 32; off <<= 1) {
        u32 n = __shfl_up_sync(0xFFFFFFFFu, v, off);
        if (l >= off) v += n;
    }
    if (l == 31) wsum[w] = v;
    __syncthreads();
    if (t == 0) {
        u32 run = 0;
        #pragma unroll
        for (int i = 0; i < 8; i++) { u32 c = wsum[i]; wsum[i] = run; run += c; }
    }
    __syncthreads();
    g_gbase[(p * SEGS + seg) * 256 + t] = wsum[w] + v - tot;
}

// ---------------- per-(seg,digit) scan over tiles (digit-major rows, coalesced) ----------------
__global__ void __launch_bounds__(256) tscan_k(int P) {
    const int seg = blockIdx.x;
    const int t = threadIdx.x, w = t >> 5, l = t & 31;
    const int d = blockIdx.y * 8 + w;
    u32* row = g_th + ((size_t)(P * SEGS + seg) * 256 + d) * TILES;
    u32 run = g_gbase[(P * SEGS + seg) * 256 + d];
    for (int c = 0; c < TILES; c += 32) {
        u32 v = row[c + l];
        u32 s = v;
        #pragma unroll
        for (int off = 1; off < 32; off <<= 1) {
            u32 n = __shfl_up_sync(0xFFFFFFFFu, s, off);
            if (l >= off) s += n;
        }
        row[c + l] = run + s - v;          // exclusive absolute offset
        run += __shfl_sync(0xFFFFFFFFu, s, 31);
    }
}

// ---------------- stable rank + direct scatter (R12 engine, parity flipped) ----------------
// counters: digit-major rows, ROWB bytes/row; cell index within row = k*8 + w
// MODE 0: sorted u64 items -> other buffer
// MODE 1: fused epilogue  out[idx] = t_sorted[pos]   (samples, pass 3)
// MODE 2: g_tval[pos] = key-as-float                 (template, pass 3)
template<int PASS, int MODE>
__global__ void __launch_bounds__(TPB, 3) scatter_k(float* __restrict__ outf, int segOff) {
    __shared__ __align__(16) u32 cnt32[256 * ROWB / 4];   // 33 KB, digit-major, padded rows
    __shared__ u32 rb[IPT * 256];                         // 16 KB: abs base per (round, digit)
    u8* cnt8 = reinterpret_cast<u8*>(cnt32);

    const int t = threadIdx.x;
    const int w = t >> 5;
    const int l = t & 31;
    const u32 lmlt = (1u << l) - 1u;
    const u32 tile = blockIdx.x;
    const int seg = blockIdx.y + segOff;
    constexpr int SHIFT = 32 + 8 * PASS;

    const u64* __restrict__ in = (PASS & 1) ? g_bufA : g_bufB;
    u64* __restrict__ outp     = (PASS & 1) ? g_bufB : g_bufA;
    const size_t sbase = (size_t)seg * NSEG;
    const size_t base = sbase + (size_t)tile * TILE;

    // issue global loads early (striped; streaming hint)
    u64 item[IPT];
    #pragma unroll
    for (int k = 0; k < IPT; k++) item[k] = __ldcs(&in[base + (size_t)k * TPB + t]);

    // absolute digit base for this (seg, digit t, tile) — precomputed, no lookback
    u32 run = g_th[((size_t)(PASS * SEGS + seg) * 256 + t) * TILES + tile];

    // zero counters (256*33 = 8448 words = 33 per thread)
    #pragma unroll
    for (int i = 0; i < (256 * ROWB / 4) / TPB; i++) cnt32[i * TPB + t] = 0;
    __syncthreads();

    // warp match ranking; leaders record per-(round,warp,digit) counts
    u32 lr0 = 0, lr1 = 0, lr2 = 0, lr3 = 0;
    #pragma unroll
    for (int k = 0; k < IPT; k++) {
        u32 d = (u32)(item[k] >> SHIFT) & 255u;
        u32 m = __match_any_sync(0xFFFFFFFFu, d);
        u32 r = __popc(m & lmlt);
        if (r == 0) cnt8[d * ROWB + k * 8 + w] = (u8)__popc(m);
        if (k < 4)       lr0 |= r << (8 * k);
        else if (k < 8)  lr1 |= r << (8 * (k - 4));
        else if (k < 12) lr2 |= r << (8 * (k - 8));
        else             lr3 |= r << (8 * (k - 12));
    }
    __syncthreads();

    // thread t owns digit t: SIMD byte-prefix over 16 rounds x 2 words
    {
        const u32 rowW = (u32)t * (ROWB / 4);
        #pragma unroll
        for (int k = 0; k < IPT; k++) {
            rb[k * 256 + t] = run;
            u32 w0 = cnt32[rowW + k * 2];
            u32 w1 = cnt32[rowW + k * 2 + 1];
            u32 s0 = w0 * 0x01010101u;           // inclusive byte prefix of cells 0..3
            u32 s1 = w1 * 0x01010101u;           // inclusive byte prefix of cells 4..7
            u32 sum0 = s0 >> 24;
            cnt32[rowW + k * 2]     = s0 << 8;                       // exclusive prefixes
            cnt32[rowW + k * 2 + 1] = (s1 << 8) + sum0 * 0x01010101u;
            run += sum0 + (s1 >> 24);
        }
    }
    __syncthreads();

    // final positions, direct global write
    #pragma unroll
    for (int k = 0; k < IPT; k++) {
        u32 d = (u32)(item[k] >> SHIFT) & 255u;
        u32 r;
        if (k < 4)       r = (lr0 >> (8 * k)) & 255u;
        else if (k < 8)  r = (lr1 >> (8 * (k - 4))) & 255u;
        else if (k < 12) r = (lr2 >> (8 * (k - 8))) & 255u;
        else             r = (lr3 >> (8 * (k - 12))) & 255u;
        u32 pos = rb[k * 256 + d] + (u32)cnt8[d * ROWB + k * 8 + w] + r;
        if (MODE == 0) {
            outp[sbase + pos] = item[k];
        } else if (MODE == 2) {
            g_tval[pos] = k2f((u32)(item[k] >> 32));
        } else {
            outf[sbase + (u32)item[k]] = __ldg(&g_tval[pos]);
        }
    }
}

extern "C" void kernel_launch(void* const* d_in, const int* in_sizes, int n_in,
                              void* d_out, int out_size) {
    const float* x  = (const float*)d_in[0];
    const float* bv = (const float*)d_in[1];
    float* out = (float*)d_out;

    zero_k<<<36, 256>>>();
    pack_hist_k<<<dim3(TILES, SEGS), TPB>>>(x, bv);
    gscan_k<<<dim3(SEGS, 3), 256>>>();

    // pass 1: byte 1   A -> B   (per-tile hist from pack)
    tscan_k<<<dim3(SEGS, 32), 256>>>(1);
    scatter_k<1, 0><<<dim3(TILES, SEGS), TPB>>>(nullptr, 0);

    // pass 2: byte 2   B -> A
    hist_k<2><<<dim3(TILES, SEGS), TPB>>>();
    tscan_k<<<dim3(SEGS, 32), 256>>>(2);
    scatter_k<2, 0><<<dim3(TILES, SEGS), TPB>>>(nullptr, 0);

    // pass 3: byte 3   A -> final
    hist_k<3><<<dim3(TILES, SEGS), TPB>>>();
    tscan_k<<<dim3(SEGS, 32), 256>>>(3);
    scatter_k<3, 2><<<dim3(TILES, 1), TPB>>>(nullptr, NSAMP);  // template -> g_tval
    scatter_k<3, 1><<<dim3(TILES, NSAMP), TPB>>>(out, 0);      // fused epilogue
}

// round 14
// speedup vs baseline: 27.8593x; 1.0102x over previous
#include <cuda_runtime.h>

typedef unsigned int u32;
typedef unsigned long long u64;
typedef unsigned char u8;

#define NSEG 2621440u      // voxels per sample == template size
#define NSAMP 8
#define SEGS 9             // 8 samples + 1 template
#define TPB 256
#define IPT 16
#define TILE 4096          // TPB*IPT
#define TILES 640          // NSEG / TILE (exact)
#define ROWB 132           // padded bytes per digit row (33 words -> conflict-free)

// Static device scratch
__device__ u64 g_bufA[(size_t)SEGS * NSEG];
__device__ u64 g_bufB[(size_t)SEGS * NSEG];
__device__ u32 g_th[4ull * SEGS * 256 * TILES];  // [pass][seg][digit][tile] counts -> abs offsets
__device__ u32 g_ghist[4 * SEGS * 256];          // global digit hist per (pass,seg)
__device__ u32 g_gbase[4 * SEGS * 256];          // exclusive scan of g_ghist
__device__ float g_tval[NSEG];                   // sorted template values

__device__ __forceinline__ u32 f2k(float f) {
    u32 u = __float_as_uint(f);
    return u ^ ((u & 0x80000000u) ? 0xFFFFFFFFu : 0x80000000u);
}
__device__ __forceinline__ float k2f(u32 u) {
    u ^= ((u & 0x80000000u) ? 0x80000000u : 0xFFFFFFFFu);
    return __uint_as_float(u);
}

// ---------------- zero global hists ----------------
__global__ void zero_k() {
    u32 i = blockIdx.x * blockDim.x + threadIdx.x;
    if (i < 4 * SEGS * 256) g_ghist[i] = 0;
}

// ---------------- hist-only: global hists (planes 1..3) + plane-1 per-tile hist ----------------
__global__ void __launch_bounds__(TPB) pack_hist_k(const float* __restrict__ x,
                                                   const float* __restrict__ t) {
    __shared__ u32 h[3][256];   // planes 1,2,3
    const int tid = threadIdx.x;
    const int l = tid & 31;
    const int seg = blockIdx.y;
    const int tile = blockIdx.x;
    for (int i = tid; i < 3 * 256; i += TPB) (&h[0][0])[i] = 0;
    __syncthreads();

    const float* src = (seg < NSAMP) ? (x + (size_t)seg * NSEG) : t;
    const u32 base = tile * TILE;
    #pragma unroll
    for (int k = 0; k < 4; k++) {
        u32 j = base + (u32)(k * TPB * 4) + tid * 4;
        float4 v = *reinterpret_cast<const float4*>(src + j);
        u32 kk[4] = { f2k(v.x), f2k(v.y), f2k(v.z), f2k(v.w) };
        #pragma unroll
        for (int e = 0; e < 4; e++) {
            atomicAdd(&h[0][(kk[e] >> 8) & 255u], 1u);   // plane 1 (byte 1)
            u32 d2 = (kk[e] >> 16) & 255u;               // plane 2 (skewed): aggregate
            u32 m2 = __match_any_sync(0xFFFFFFFFu, d2);
            if ((int)(__ffs(m2) - 1) == l) atomicAdd(&h[1][d2], (u32)__popc(m2));
            u32 d3 = kk[e] >> 24;                        // plane 3 (skewed): aggregate
            u32 m3 = __match_any_sync(0xFFFFFFFFu, d3);
            if ((int)(__ffs(m3) - 1) == l) atomicAdd(&h[2][d3], (u32)__popc(m3));
        }
    }
    __syncthreads();
    #pragma unroll
    for (int p = 0; p < 3; p++) {
        u32 c = h[p][tid];
        if (c) atomicAdd(&g_ghist[((p + 1) * SEGS + seg) * 256 + tid], c);
    }
    // plane-1 per-tile hist (first sort pass)
    g_th[((size_t)(1 * SEGS + seg) * 256 + tid) * TILES + tile] = h[0][tid];
}

// ---------------- per-tile hist for passes 2..3 (reads key u32 only) ----------------
// parity: pass1 floats->B, pass2 B->A, pass3 A->out  =>  input = (PASS&1) ? A : B
template<int PASS>
__global__ void __launch_bounds__(TPB) hist_k() {
    __shared__ u32 h[8][256];
    const u32* __restrict__ in = reinterpret_cast<const u32*>((PASS & 1) ? g_bufA : g_bufB);
    const int t = threadIdx.x;
    const int w = t >> 5;
    const int tile = blockIdx.x, seg = blockIdx.y;
    #pragma unroll
    for (int i = t; i < 8 * 256; i += TPB) (&h[0][0])[i] = 0;
    __syncthreads();
    const size_t base = 2 * ((size_t)seg * NSEG + (size_t)tile * TILE) + 1;
    #pragma unroll
    for (int k = 0; k < IPT; k++) {
        u32 key = __ldcs(&in[base + 2 * (size_t)(k * TPB + t)]);
        atomicAdd(&h[w][(key >> (8 * PASS)) & 255u], 1u);
    }
    __syncthreads();
    u32 s = 0;
    #pragma unroll
    for (int w2 = 0; w2 < 8; w2++) s += h[w2][t];
    g_th[((size_t)(PASS * SEGS + seg) * 256 + t) * TILES + tile] = s;
}

// ---------------- per-(pass,seg) exclusive digit scan (planes 1..3) ----------------
__global__ void gscan_k() {
    __shared__ u32 wsum[8];
    const int seg = blockIdx.x, p = blockIdx.y + 1;
    const int t = threadIdx.x, l = t & 31, w = t >> 5;
    u32 tot = g_ghist[(p * SEGS + seg) * 256 + t];
    u32 v = tot;
    #pragma unroll
    for (int off = 1; off < 32; off <<= 1) {
        u32 n = __shfl_up_sync(0xFFFFFFFFu, v, off);
        if (l >= off) v += n;
    }
    if (l == 31) wsum[w] = v;
    __syncthreads();
    if (t == 0) {
        u32 run = 0;
        #pragma unroll
        for (int i = 0; i < 8; i++) { u32 c = wsum[i]; wsum[i] = run; run += c; }
    }
    __syncthreads();
    g_gbase[(p * SEGS + seg) * 256 + t] = wsum[w] + v - tot;
}

// ---------------- per-(seg,digit) scan over tiles (digit-major rows, coalesced) ----------------
__global__ void __launch_bounds__(256) tscan_k(int P) {
    const int seg = blockIdx.x;
    const int t = threadIdx.x, w = t >> 5, l = t & 31;
    const int d = blockIdx.y * 8 + w;
    u32* row = g_th + ((size_t)(P * SEGS + seg) * 256 + d) * TILES;
    u32 run = g_gbase[(P * SEGS + seg) * 256 + d];
    for (int c = 0; c < TILES; c += 32) {
        u32 v = row[c + l];
        u32 s = v;
        #pragma unroll
        for (int off = 1; off < 32; off <<= 1) {
            u32 n = __shfl_up_sync(0xFFFFFFFFu, s, off);
            if (l >= off) s += n;
        }
        row[c + l] = run + s - v;          // exclusive absolute offset
        run += __shfl_sync(0xFFFFFFFFu, s, 31);
    }
}

// ---------------- pass-1 scatter: reads raw floats, writes u64 records to B ----------------
__global__ void __launch_bounds__(TPB, 3) scatter0_k(const float* __restrict__ x,
                                                     const float* __restrict__ bv) {
    __shared__ __align__(16) u32 cnt32[256 * ROWB / 4];   // 33 KB, digit-major, padded rows
    __shared__ u32 rb[IPT * 256];                         // 16 KB
    u8* cnt8 = reinterpret_cast<u8*>(cnt32);

    const int t = threadIdx.x;
    const int w = t >> 5;
    const int l = t & 31;
    const u32 lmlt = (1u << l) - 1u;
    const u32 tile = blockIdx.x;
    const int seg = blockIdx.y;           // 0..8 (8 = template)

    const float* __restrict__ src = (seg < NSAMP) ? (x + (size_t)seg * NSEG) : bv;
    u64* __restrict__ outp = g_bufB;
    const size_t sbase = (size_t)seg * NSEG;
    const u32 jb = tile * TILE;

    // load floats, make keys (payload = position, recomputed at write)
    u32 key[IPT];
    #pragma unroll
    for (int k = 0; k < IPT; k++) key[k] = f2k(__ldcs(&src[jb + (u32)k * TPB + t]));

    u32 run = g_th[((size_t)(1 * SEGS + seg) * 256 + t) * TILES + tile];

    #pragma unroll
    for (int i = 0; i < (256 * ROWB / 4) / TPB; i++) cnt32[i * TPB + t] = 0;
    __syncthreads();

    u32 lr0 = 0, lr1 = 0, lr2 = 0, lr3 = 0;
    #pragma unroll
    for (int k = 0; k < IPT; k++) {
        u32 d = (key[k] >> 8) & 255u;
        u32 m = __match_any_sync(0xFFFFFFFFu, d);
        u32 r = __popc(m & lmlt);
        if (r == 0) cnt8[d * ROWB + k * 8 + w] = (u8)__popc(m);
        if (k < 4)       lr0 |= r << (8 * k);
        else if (k < 8)  lr1 |= r << (8 * (k - 4));
        else if (k < 12) lr2 |= r << (8 * (k - 8));
        else             lr3 |= r << (8 * (k - 12));
    }
    __syncthreads();

    {
        const u32 rowW = (u32)t * (ROWB / 4);
        #pragma unroll
        for (int k = 0; k < IPT; k++) {
            rb[k * 256 + t] = run;
            u32 w0 = cnt32[rowW + k * 2];
            u32 w1 = cnt32[rowW + k * 2 + 1];
            u32 s0 = w0 * 0x01010101u;
            u32 s1 = w1 * 0x01010101u;
            u32 sum0 = s0 >> 24;
            cnt32[rowW + k * 2]     = s0 << 8;
            cnt32[rowW + k * 2 + 1] = (s1 << 8) + sum0 * 0x01010101u;
            run += sum0 + (s1 >> 24);
        }
    }
    __syncthreads();

    #pragma unroll
    for (int k = 0; k < IPT; k++) {
        u32 d = (key[k] >> 8) & 255u;
        u32 r;
        if (k < 4)       r = (lr0 >> (8 * k)) & 255u;
        else if (k < 8)  r = (lr1 >> (8 * (k - 4))) & 255u;
        else if (k < 12) r = (lr2 >> (8 * (k - 8))) & 255u;
        else             r = (lr3 >> (8 * (k - 12))) & 255u;
        u32 pos = rb[k * 256 + d] + (u32)cnt8[d * ROWB + k * 8 + w] + r;
        outp[sbase + pos] = ((u64)key[k] << 32) | (jb + (u32)k * TPB + t);
    }
}

// ---------------- stable rank + direct scatter (R12 engine; passes 2..3) ----------------
// parity: pass2 B->A, pass3 A->final
// MODE 0: sorted u64 items -> other buffer
// MODE 1: fused epilogue  out[idx] = t_sorted[pos]   (samples, pass 3)
// MODE 2: g_tval[pos] = key-as-float                 (template, pass 3)
template<int PASS, int MODE>
__global__ void __launch_bounds__(TPB, 3) scatter_k(float* __restrict__ outf, int segOff) {
    __shared__ __align__(16) u32 cnt32[256 * ROWB / 4];   // 33 KB
    __shared__ u32 rb[IPT * 256];                         // 16 KB
    u8* cnt8 = reinterpret_cast<u8*>(cnt32);

    const int t = threadIdx.x;
    const int w = t >> 5;
    const int l = t & 31;
    const u32 lmlt = (1u << l) - 1u;
    const u32 tile = blockIdx.x;
    const int seg = blockIdx.y + segOff;
    constexpr int SHIFT = 32 + 8 * PASS;

    const u64* __restrict__ in = (PASS & 1) ? g_bufA : g_bufB;
    u64* __restrict__ outp     = (PASS & 1) ? g_bufB : g_bufA;
    const size_t sbase = (size_t)seg * NSEG;
    const size_t base = sbase + (size_t)tile * TILE;

    u64 item[IPT];
    #pragma unroll
    for (int k = 0; k < IPT; k++) item[k] = __ldcs(&in[base + (size_t)k * TPB + t]);

    u32 run = g_th[((size_t)(PASS * SEGS + seg) * 256 + t) * TILES + tile];

    #pragma unroll
    for (int i = 0; i < (256 * ROWB / 4) / TPB; i++) cnt32[i * TPB + t] = 0;
    __syncthreads();

    u32 lr0 = 0, lr1 = 0, lr2 = 0, lr3 = 0;
    #pragma unroll
    for (int k = 0; k < IPT; k++) {
        u32 d = (u32)(item[k] >> SHIFT) & 255u;
        u32 m = __match_any_sync(0xFFFFFFFFu, d);
        u32 r = __popc(m & lmlt);
        if (r == 0) cnt8[d * ROWB + k * 8 + w] = (u8)__popc(m);
        if (k < 4)       lr0 |= r << (8 * k);
        else if (k < 8)  lr1 |= r << (8 * (k - 4));
        else if (k < 12) lr2 |= r << (8 * (k - 8));
        else             lr3 |= r << (8 * (k - 12));
    }
    __syncthreads();

    {
        const u32 rowW = (u32)t * (ROWB / 4);
        #pragma unroll
        for (int k = 0; k < IPT; k++) {
            rb[k * 256 + t] = run;
            u32 w0 = cnt32[rowW + k * 2];
            u32 w1 = cnt32[rowW + k * 2 + 1];
            u32 s0 = w0 * 0x01010101u;
            u32 s1 = w1 * 0x01010101u;
            u32 sum0 = s0 >> 24;
            cnt32[rowW + k * 2]     = s0 << 8;
            cnt32[rowW + k * 2 + 1] = (s1 << 8) + sum0 * 0x01010101u;
            run += sum0 + (s1 >> 24);
        }
    }
    __syncthreads();

    #pragma unroll
    for (int k = 0; k < IPT; k++) {
        u32 d = (u32)(item[k] >> SHIFT) & 255u;
        u32 r;
        if (k < 4)       r = (lr0 >> (8 * k)) & 255u;
        else if (k < 8)  r = (lr1 >> (8 * (k - 4))) & 255u;
        else if (k < 12) r = (lr2 >> (8 * (k - 8))) & 255u;
        else             r = (lr3 >> (8 * (k - 12))) & 255u;
        u32 pos = rb[k * 256 + d] + (u32)cnt8[d * ROWB + k * 8 + w] + r;
        if (MODE == 0) {
            outp[sbase + pos] = item[k];
        } else if (MODE == 2) {
            g_tval[pos] = k2f((u32)(item[k] >> 32));
        } else {
            outf[sbase + (u32)item[k]] = __ldg(&g_tval[pos]);
        }
    }
}

extern "C" void kernel_launch(void* const* d_in, const int* in_sizes, int n_in,
                              void* d_out, int out_size) {
    const float* x  = (const float*)d_in[0];
    const float* bv = (const float*)d_in[1];
    float* out = (float*)d_out;

    zero_k<<<36, 256>>>();
    pack_hist_k<<<dim3(TILES, SEGS), TPB>>>(x, bv);
    gscan_k<<<dim3(SEGS, 3), 256>>>();

    // pass 1: byte 1   floats -> B   (fused pack; per-tile hist from pack_hist)
    tscan_k<<<dim3(SEGS, 32), 256>>>(1);
    scatter0_k<<<dim3(TILES, SEGS), TPB>>>(x, bv);

    // pass 2: byte 2   B -> A
    hist_k<2><<<dim3(TILES, SEGS), TPB>>>();
    tscan_k<<<dim3(SEGS, 32), 256>>>(2);
    scatter_k<2, 0><<<dim3(TILES, SEGS), TPB>>>(nullptr, 0);

    // pass 3: byte 3   A -> final
    hist_k<3><<<dim3(TILES, SEGS), TPB>>>();
    tscan_k<<<dim3(SEGS, 32), 256>>>(3);
    scatter_k<3, 2><<<dim3(TILES, 1), TPB>>>(nullptr, NSAMP);  // template -> g_tval
    scatter_k<3, 1><<<dim3(TILES, NSAMP), TPB>>>(out, 0);      // fused epilogue
}

// round 15
// speedup vs baseline: 28.0537x; 1.0070x over previous
#include <cuda_runtime.h>

typedef unsigned int u32;
typedef unsigned long long u64;
typedef unsigned char u8;

#define NSEG 2621440u      // voxels per sample == template size
#define NSAMP 8
#define SEGS 9             // 8 samples + 1 template
#define TPB 256            // hist / scan kernels
#define STPB 512           // scatter kernels
#define IPT 16             // hist items per thread
#define SIPT 8             // scatter items per thread (512*8 = 4096)
#define LR 16              // logical rounds in scatter engine (2 halves x 8)
#define TILE 4096
#define TILES 640          // NSEG / TILE (exact)
#define ROWB 132           // padded bytes per digit row (33 words -> conflict-free)
#define CNTW (256 * ROWB / 4)   // 8448 words

// Static device scratch
__device__ u64 g_bufA[(size_t)SEGS * NSEG];
__device__ u64 g_bufB[(size_t)SEGS * NSEG];
__device__ u32 g_th[4ull * SEGS * 256 * TILES];  // [pass][seg][digit][tile] counts -> abs offsets
__device__ u32 g_ghist[4 * SEGS * 256];          // global digit hist per (pass,seg)
__device__ u32 g_gbase[4 * SEGS * 256];          // exclusive scan of g_ghist
__device__ float g_tval[NSEG];                   // sorted template values

__device__ __forceinline__ u32 f2k(float f) {
    u32 u = __float_as_uint(f);
    return u ^ ((u & 0x80000000u) ? 0xFFFFFFFFu : 0x80000000u);
}
__device__ __forceinline__ float k2f(u32 u) {
    u ^= ((u & 0x80000000u) ? 0x80000000u : 0xFFFFFFFFu);
    return __uint_as_float(u);
}

// ---------------- zero global hists ----------------
__global__ void zero_k() {
    u32 i = blockIdx.x * blockDim.x + threadIdx.x;
    if (i < 4 * SEGS * 256) g_ghist[i] = 0;
}

// ---------------- hist-only: global hists (planes 1..3) + plane-1 per-tile hist ----------------
__global__ void __launch_bounds__(TPB) pack_hist_k(const float* __restrict__ x,
                                                   const float* __restrict__ t) {
    __shared__ u32 h[3][256];   // planes 1,2,3
    const int tid = threadIdx.x;
    const int l = tid & 31;
    const int seg = blockIdx.y;
    const int tile = blockIdx.x;
    for (int i = tid; i < 3 * 256; i += TPB) (&h[0][0])[i] = 0;
    __syncthreads();

    const float* src = (seg < NSAMP) ? (x + (size_t)seg * NSEG) : t;
    const u32 base = tile * TILE;
    #pragma unroll
    for (int k = 0; k < 4; k++) {
        u32 j = base + (u32)(k * TPB * 4) + tid * 4;
        float4 v = *reinterpret_cast<const float4*>(src + j);
        u32 kk[4] = { f2k(v.x), f2k(v.y), f2k(v.z), f2k(v.w) };
        #pragma unroll
        for (int e = 0; e < 4; e++) {
            atomicAdd(&h[0][(kk[e] >> 8) & 255u], 1u);   // plane 1 (byte 1)
            u32 d2 = (kk[e] >> 16) & 255u;               // plane 2 (skewed): aggregate
            u32 m2 = __match_any_sync(0xFFFFFFFFu, d2);
            if ((int)(__ffs(m2) - 1) == l) atomicAdd(&h[1][d2], (u32)__popc(m2));
            u32 d3 = kk[e] >> 24;                        // plane 3 (skewed): aggregate
            u32 m3 = __match_any_sync(0xFFFFFFFFu, d3);
            if ((int)(__ffs(m3) - 1) == l) atomicAdd(&h[2][d3], (u32)__popc(m3));
        }
    }
    __syncthreads();
    #pragma unroll
    for (int p = 0; p < 3; p++) {
        u32 c = h[p][tid];
        if (c) atomicAdd(&g_ghist[((p + 1) * SEGS + seg) * 256 + tid], c);
    }
    // plane-1 per-tile hist (first sort pass)
    g_th[((size_t)(1 * SEGS + seg) * 256 + tid) * TILES + tile] = h[0][tid];
}

// ---------------- per-tile hist for passes 2..3 (reads key u32 only) ----------------
// parity: pass1 floats->B, pass2 B->A, pass3 A->out  =>  input = (PASS&1) ? A : B
// PASS 3 digit (byte 3) is heavily skewed -> warp-aggregate atomics
template<int PASS>
__global__ void __launch_bounds__(TPB) hist_k() {
    __shared__ u32 h[8][256];
    const u32* __restrict__ in = reinterpret_cast<const u32*>((PASS & 1) ? g_bufA : g_bufB);
    const int t = threadIdx.x;
    const int w = t >> 5;
    const int l = t & 31;
    const int tile = blockIdx.x, seg = blockIdx.y;
    #pragma unroll
    for (int i = t; i < 8 * 256; i += TPB) (&h[0][0])[i] = 0;
    __syncthreads();
    const size_t base = 2 * ((size_t)seg * NSEG + (size_t)tile * TILE) + 1;
    #pragma unroll
    for (int k = 0; k < IPT; k++) {
        u32 key = __ldcs(&in[base + 2 * (size_t)(k * TPB + t)]);
        u32 d = (key >> (8 * PASS)) & 255u;
        if (PASS == 3) {   // skewed digits: aggregate before atomic
            u32 m = __match_any_sync(0xFFFFFFFFu, d);
            if ((int)(__ffs(m) - 1) == l) atomicAdd(&h[w][d], (u32)__popc(m));
        } else {
            atomicAdd(&h[w][d], 1u);
        }
    }
    __syncthreads();
    u32 s = 0;
    #pragma unroll
    for (int w2 = 0; w2 < 8; w2++) s += h[w2][t];
    g_th[((size_t)(PASS * SEGS + seg) * 256 + t) * TILES + tile] = s;
}

// ---------------- per-(pass,seg) exclusive digit scan (planes 1..3) ----------------
__global__ void gscan_k() {
    __shared__ u32 wsum[8];
    const int seg = blockIdx.x, p = blockIdx.y + 1;
    const int t = threadIdx.x, l = t & 31, w = t >> 5;
    u32 tot = g_ghist[(p * SEGS + seg) * 256 + t];
    u32 v = tot;
    #pragma unroll
    for (int off = 1; off < 32; off <<= 1) {
        u32 n = __shfl_up_sync(0xFFFFFFFFu, v, off);
        if (l >= off) v += n;
    }
    if (l == 31) wsum[w] = v;
    __syncthreads();
    if (t == 0) {
        u32 run = 0;
        #pragma unroll
        for (int i = 0; i < 8; i++) { u32 c = wsum[i]; wsum[i] = run; run += c; }
    }
    __syncthreads();
    g_gbase[(p * SEGS + seg) * 256 + t] = wsum[w] + v - tot;
}

// ---------------- per-(seg,digit) scan over tiles (digit-major rows, coalesced) ----------------
__global__ void __launch_bounds__(256) tscan_k(int P) {
    const int seg = blockIdx.x;
    const int t = threadIdx.x, w = t >> 5, l = t & 31;
    const int d = blockIdx.y * 8 + w;
    u32* row = g_th + ((size_t)(P * SEGS + seg) * 256 + d) * TILES;
    u32 run = g_gbase[(P * SEGS + seg) * 256 + d];
    for (int c = 0; c < TILES; c += 32) {
        u32 v = row[c + l];
        u32 s = v;
        #pragma unroll
        for (int off = 1; off < 32; off <<= 1) {
            u32 n = __shfl_up_sync(0xFFFFFFFFu, s, off);
            if (l >= off) s += n;
        }
        row[c + l] = run + s - v;          // exclusive absolute offset
        run += __shfl_sync(0xFFFFFFFFu, s, 31);
    }
}

// ======================================================================
// 512-thread scatter engine. Warp w: half h = w>>3, slot wl = w&7.
// Thread's k-th item is logical round R = h*8+k; element j = R*256 + wl*32 + l
// (ascending j == (R, wl, l) lexicographic -> stable).
// Counter layout identical to R12: 128 u8 cells per digit row (cell = R*8+wl).
// ======================================================================

// ---------------- pass-1 scatter: raw floats -> u64 records in B ----------------
__global__ void __launch_bounds__(STPB, 2) scatter0_k(const float* __restrict__ x,
                                                      const float* __restrict__ bv) {
    __shared__ __align__(16) u32 cnt32[CNTW];   // 33 KB
    __shared__ u32 rb[LR * 256];                // 16 KB
    u8* cnt8 = reinterpret_cast<u8*>(cnt32);

    const int t = threadIdx.x;
    const int w = t >> 5;
    const int l = t & 31;
    const int wl = w & 7;
    const int h = w >> 3;
    const u32 lmlt = (1u << l) - 1u;
    const u32 tile = blockIdx.x;
    const int seg = blockIdx.y;

    const float* __restrict__ src = (seg < NSAMP) ? (x + (size_t)seg * NSEG) : bv;
    const size_t sbase = (size_t)seg * NSEG;
    const u32 jb = tile * TILE;
    const u32 jo = (u32)h * 2048 + (u32)wl * 32 + l;   // + k*256

    u32 key[SIPT];
    #pragma unroll
    for (int k = 0; k < SIPT; k++) key[k] = f2k(__ldcs(&src[jb + jo + (u32)k * 256]));

    u32 run = (t < 256) ? g_th[((size_t)(1 * SEGS + seg) * 256 + t) * TILES + tile] : 0u;

    #pragma unroll
    for (int i = 0; i < 17; i++) {
        u32 idx = (u32)i * STPB + t;
        if (idx < CNTW) cnt32[idx] = 0;
    }
    __syncthreads();

    u32 lr0 = 0, lr1 = 0;
    #pragma unroll
    for (int k = 0; k < SIPT; k++) {
        u32 d = (key[k] >> 8) & 255u;
        u32 m = __match_any_sync(0xFFFFFFFFu, d);
        u32 r = __popc(m & lmlt);
        if (r == 0) cnt8[d * ROWB + (h * 8 + k) * 8 + wl] = (u8)__popc(m);
        if (k < 4) lr0 |= r << (8 * k);
        else       lr1 |= r << (8 * (k - 4));
    }
    __syncthreads();

    if (t < 256) {
        const u32 rowW = (u32)t * (ROWB / 4);
        #pragma unroll
        for (int k = 0; k < LR; k++) {
            rb[k * 256 + t] = run;
            u32 w0 = cnt32[rowW + k * 2];
            u32 w1 = cnt32[rowW + k * 2 + 1];
            u32 s0 = w0 * 0x01010101u;
            u32 s1 = w1 * 0x01010101u;
            u32 sum0 = s0 >> 24;
            cnt32[rowW + k * 2]     = s0 << 8;
            cnt32[rowW + k * 2 + 1] = (s1 << 8) + sum0 * 0x01010101u;
            run += sum0 + (s1 >> 24);
        }
    }
    __syncthreads();

    #pragma unroll
    for (int k = 0; k < SIPT; k++) {
        u32 d = (key[k] >> 8) & 255u;
        u32 r = (k < 4) ? ((lr0 >> (8 * k)) & 255u) : ((lr1 >> (8 * (k - 4))) & 255u);
        u32 R = (u32)(h * 8 + k);
        u32 pos = rb[R * 256 + d] + (u32)cnt8[d * ROWB + R * 8 + wl] + r;
        g_bufB[sbase + pos] = ((u64)key[k] << 32) | (jb + jo + (u32)k * 256);
    }
}

// ---------------- passes 2..3 scatter over u64 items ----------------
// parity: pass2 B->A, pass3 A->final
// MODE 0: sorted u64 -> other buffer   MODE 1: out[idx] = g_tval[pos]   MODE 2: g_tval[pos] = key
template<int PASS, int MODE>
__global__ void __launch_bounds__(STPB, 2) scatter_k(float* __restrict__ outf, int segOff) {
    __shared__ __align__(16) u32 cnt32[CNTW];   // 33 KB
    __shared__ u32 rb[LR * 256];                // 16 KB
    u8* cnt8 = reinterpret_cast<u8*>(cnt32);

    const int t = threadIdx.x;
    const int w = t >> 5;
    const int l = t & 31;
    const int wl = w & 7;
    const int h = w >> 3;
    const u32 lmlt = (1u << l) - 1u;
    const u32 tile = blockIdx.x;
    const int seg = blockIdx.y + segOff;
    constexpr int SHIFT = 32 + 8 * PASS;

    const u64* __restrict__ in = (PASS & 1) ? g_bufA : g_bufB;
    u64* __restrict__ outp     = (PASS & 1) ? g_bufB : g_bufA;
    const size_t sbase = (size_t)seg * NSEG;
    const size_t base = sbase + (size_t)tile * TILE;
    const u32 jo = (u32)h * 2048 + (u32)wl * 32 + l;   // + k*256

    u64 item[SIPT];
    #pragma unroll
    for (int k = 0; k < SIPT; k++) item[k] = __ldcs(&in[base + jo + (u32)k * 256]);

    u32 run = (t < 256) ? g_th[((size_t)(PASS * SEGS + seg) * 256 + t) * TILES + tile] : 0u;

    #pragma unroll
    for (int i = 0; i < 17; i++) {
        u32 idx = (u32)i * STPB + t;
        if (idx < CNTW) cnt32[idx] = 0;
    }
    __syncthreads();

    u32 lr0 = 0, lr1 = 0;
    #pragma unroll
    for (int k = 0; k < SIPT; k++) {
        u32 d = (u32)(item[k] >> SHIFT) & 255u;
        u32 m = __match_any_sync(0xFFFFFFFFu, d);
        u32 r = __popc(m & lmlt);
        if (r == 0) cnt8[d * ROWB + (h * 8 + k) * 8 + wl] = (u8)__popc(m);
        if (k < 4) lr0 |= r << (8 * k);
        else       lr1 |= r << (8 * (k - 4));
    }
    __syncthreads();

    if (t < 256) {
        const u32 rowW = (u32)t * (ROWB / 4);
        #pragma unroll
        for (int k = 0; k < LR; k++) {
            rb[k * 256 + t] = run;
            u32 w0 = cnt32[rowW + k * 2];
            u32 w1 = cnt32[rowW + k * 2 + 1];
            u32 s0 = w0 * 0x01010101u;
            u32 s1 = w1 * 0x01010101u;
            u32 sum0 = s0 >> 24;
            cnt32[rowW + k * 2]     = s0 << 8;
            cnt32[rowW + k * 2 + 1] = (s1 << 8) + sum0 * 0x01010101u;
            run += sum0 + (s1 >> 24);
        }
    }
    __syncthreads();

    #pragma unroll
    for (int k = 0; k < SIPT; k++) {
        u32 d = (u32)(item[k] >> SHIFT) & 255u;
        u32 r = (k < 4) ? ((lr0 >> (8 * k)) & 255u) : ((lr1 >> (8 * (k - 4))) & 255u);
        u32 R = (u32)(h * 8 + k);
        u32 pos = rb[R * 256 + d] + (u32)cnt8[d * ROWB + R * 8 + wl] + r;
        if (MODE == 0) {
            outp[sbase + pos] = item[k];
        } else if (MODE == 2) {
            g_tval[pos] = k2f((u32)(item[k] >> 32));
        } else {
            outf[sbase + (u32)item[k]] = __ldg(&g_tval[pos]);
        }
    }
}

extern "C" void kernel_launch(void* const* d_in, const int* in_sizes, int n_in,
                              void* d_out, int out_size) {
    const float* x  = (const float*)d_in[0];
    const float* bv = (const float*)d_in[1];
    float* out = (float*)d_out;

    zero_k<<<36, 256>>>();
    pack_hist_k<<<dim3(TILES, SEGS), TPB>>>(x, bv);
    gscan_k<<<dim3(SEGS, 3), 256>>>();

    // pass 1: byte 1   floats -> B   (fused pack; per-tile hist from pack_hist)
    tscan_k<<<dim3(SEGS, 32), 256>>>(1);
    scatter0_k<<<dim3(TILES, SEGS), STPB>>>(x, bv);

    // pass 2: byte 2   B -> A
    hist_k<2><<<dim3(TILES, SEGS), TPB>>>();
    tscan_k<<<dim3(SEGS, 32), 256>>>(2);
    scatter_k<2, 0><<<dim3(TILES, SEGS), STPB>>>(nullptr, 0);

    // pass 3: byte 3   A -> final
    hist_k<3><<<dim3(TILES, SEGS), TPB>>>();
    tscan_k<<<dim3(SEGS, 32), 256>>>(3);
    scatter_k<3, 2><<<dim3(TILES, 1), STPB>>>(nullptr, NSAMP);  // template -> g_tval
    scatter_k<3, 1><<<dim3(TILES, NSAMP), STPB>>>(out, 0);      // fused epilogue
}